// round 15
// baseline (speedup 1.0000x reference)
#include <cuda_runtime.h>
#include <cuda_fp16.h>
#include <cstdint>

typedef unsigned long long u64;

// ---------------- static scratch ----------------
// activations layout: (p, b, c) : act[(p*128 + b)*256 + c]
__device__ __align__(16) float g_bufA[512 * 128 * 256];   // 67 MB
__device__ __align__(16) float g_bufB[256 * 128 * 256];   // 33.5 MB

// ---------------- helpers ----------------
__device__ __forceinline__ uint32_t s2u(const void* p) {
    uint32_t a;
    asm("{\n\t.reg .u64 t;\n\tcvta.to.shared.u64 t, %1;\n\tcvt.u32.u64 %0, t;\n\t}" : "=r"(a) : "l"(p));
    return a;
}
__device__ __forceinline__ uint32_t packh(float lo, float hi) {
    uint32_t r;
    asm("cvt.rn.f16x2.f32 %0, %1, %2;" : "=r"(r) : "f"(hi), "f"(lo));
    return r;
}
__device__ __forceinline__ void split2(float x0, float x1, uint32_t& hi, uint32_t& lo) {
    uint32_t h = packh(x0, x1);
    __half2 h2 = *(__half2*)&h;
    lo = packh(x0 - __half2float(h2.x), x1 - __half2float(h2.y));
    hi = h;
}
__device__ __forceinline__ void ldsm4(uint32_t* r, uint32_t addr) {
    asm volatile("ldmatrix.sync.aligned.m8n8.x4.shared.b16 {%0,%1,%2,%3}, [%4];"
        : "=r"(r[0]), "=r"(r[1]), "=r"(r[2]), "=r"(r[3]) : "r"(addr));
}
__device__ __forceinline__ void mma16816(float* d, const uint32_t* a, uint32_t b0, uint32_t b1) {
    asm volatile("mma.sync.aligned.m16n8k16.row.col.f32.f16.f16.f32 "
        "{%0,%1,%2,%3}, {%4,%5,%6,%7}, {%8,%9}, {%0,%1,%2,%3};"
        : "+f"(d[0]), "+f"(d[1]), "+f"(d[2]), "+f"(d[3])
        : "r"(a[0]), "r"(a[1]), "r"(a[2]), "r"(a[3]), "r"(b0), "r"(b1));
}
__device__ __forceinline__ u64 dup2(float x) {
    u64 r; unsigned xi = __float_as_uint(x);
    asm("mov.b64 %0, {%1, %2};" : "=l"(r) : "r"(xi), "r"(xi));
    return r;
}
__device__ __forceinline__ void fma2(u64& d, u64 a, u64 b) {
    asm("fma.rn.f32x2 %0, %1, %2, %0;" : "+l"(d) : "l"(a), "l"(b));
}

// ---------------- layer 0 ----------------
__global__ void layer0_kernel(const float* __restrict__ x, const float* __restrict__ w0,
                              float* __restrict__ out)
{
    __shared__ float xs[6][128];
    const int d   = blockIdx.x;
    const int tid = threadIdx.x;
#pragma unroll
    for (int i = 0; i < 3; i++) {
        int e = tid + i * 256;
        int ck = e >> 7, b = e & 127;
        int c = ck >> 1, k = ck & 1;
        xs[ck][b] = x[(b * 3 + c) * 1024 + 2 * d + k];
    }
    __syncthreads();
    const int b  = tid & 127;
    const int oh = tid >> 7;
    const float2* w2 = (const float2*)w0;
    for (int o = oh; o < 256; o += 2) {
        float acc = 0.f;
#pragma unroll
        for (int c = 0; c < 3; c++) {
            float2 wv = w2[(o * 3 + c) * 512 + d];
            acc += xs[c * 2 + 0][b] * wv.x + xs[c * 2 + 1][b] * wv.y;
        }
        out[((size_t)d * 128 + b) * 256 + o] = fmaxf(acc * 0.5773502691896258f, 0.f);
    }
}

// ---------------- layers 1..3: warp-mma fp16x3 (R14 template, proven) ----------------
template<int NS>
__global__ __launch_bounds__(256)
void lc_mma(const float* __restrict__ in, const float* __restrict__ w,
            float* __restrict__ out, int dl, int nst, float scale)
{
    constexpr int NROWS = 256 / NS;
    constexpr int CG    = 16 / NS;
    constexpr int NB    = NROWS / 64;
    constexpr uint32_t BSTG = 16384 + NROWS * 128;

    extern __shared__ __align__(1024) char smem[];
    const uint32_t sb = s2u(smem);
    const int tid  = threadIdx.x;
    const int wid  = tid >> 5, lane = tid & 31;
    const int d     = blockIdx.x;
    const int obase = blockIdx.y * NROWS;

    const int r  = tid >> 1;
    const int h  = tid & 1;
    const float*  a0p = in + ((size_t)(2 * d) * 128 + r) * 256;
    const float*  a1p = a0p + 128 * 256;
    const uint32_t rowb = (uint32_t)r * 128, xs_ = (uint32_t)(r & 7) << 4;
    const uint32_t offH0 = rowb + (((uint32_t)(2 * h) * 16) ^ xs_);
    const uint32_t offH1 = rowb + (((uint32_t)(2 * h + 1) * 16) ^ xs_);
    const uint32_t offL0 = rowb + (((uint32_t)(4 + 2 * h) * 16) ^ xs_);
    const uint32_t offL1 = rowb + (((uint32_t)(5 + 2 * h) * 16) ^ xs_);

    const int rb_ = tid & (NROWS - 1);
    const int gB  = tid / NROWS;
    const float2* w2 = (const float2*)w;
    const size_t  wrow = (size_t)(obase + rb_) * 256;
    const uint32_t rowbB = (uint32_t)rb_ * 128, xsB = (uint32_t)(rb_ & 7) << 4;
    uint32_t offBH[CG / 4], offBL[CG / 4];
#pragma unroll
    for (int gg = 0; gg < CG / 4; gg++) {
        const uint32_t cb = (uint32_t)(gB * CG + gg * 4) * 4;
        offBH[gg] = rowbB + (cb ^ xsB);
        offBL[gg] = rowbB + ((64 + cb) ^ xsB);
    }

    const uint32_t ST[2] = { sb, sb + BSTG };

    const int mh = wid & 1, nq = wid >> 1;
    const uint32_t co = (uint32_t)(lane >> 4) * 16;
    const uint32_t xa = (uint32_t)(lane & 7) << 4;
    uint32_t rA[4], rB[NB];
#pragma unroll
    for (int mi = 0; mi < 4; mi++) rA[mi] = (uint32_t)(mh * 64 + mi * 16 + (lane & 15)) * 128;
#pragma unroll
    for (int bj = 0; bj < NB; bj++)
        rB[bj] = (uint32_t)(nq * (NROWS / 4) + bj * 16 + (lane & 15)) * 128;

    float D[4][2 * NB][4];
#pragma unroll
    for (int i = 0; i < 4; i++)
#pragma unroll
        for (int j = 0; j < 2 * NB; j++)
#pragma unroll
            for (int q = 0; q < 4; q++) D[i][j][q] = 0.f;

    float  fa[16];
    float2 fb[CG];

    auto issue_loads = [&](int t) {
        const int c0a = t * 16 + 8 * h;
        *(float4*)&fa[0]  = *(const float4*)(a0p + c0a);
        *(float4*)&fa[4]  = *(const float4*)(a0p + c0a + 4);
        *(float4*)&fa[8]  = *(const float4*)(a1p + c0a);
        *(float4*)&fa[12] = *(const float4*)(a1p + c0a + 4);
        const int c0b = t * 16 + gB * CG;
#pragma unroll
        for (int j = 0; j < CG; j++)
            fb[j] = w2[(wrow + (size_t)(c0b + j)) * dl + d];
    };

    auto convert_store = [&](int buf) {
        uint32_t Ah[8], Al[8];
#pragma unroll
        for (int j = 0; j < 8; j++)
            split2(fa[j], fa[8 + j], Ah[j], Al[j]);
        const uint32_t ab = ST[buf];
        asm volatile("st.shared.v4.b32 [%0], {%1,%2,%3,%4};" :: "r"(ab + offH0), "r"(Ah[0]), "r"(Ah[1]), "r"(Ah[2]), "r"(Ah[3]));
        asm volatile("st.shared.v4.b32 [%0], {%1,%2,%3,%4};" :: "r"(ab + offH1), "r"(Ah[4]), "r"(Ah[5]), "r"(Ah[6]), "r"(Ah[7]));
        asm volatile("st.shared.v4.b32 [%0], {%1,%2,%3,%4};" :: "r"(ab + offL0), "r"(Al[0]), "r"(Al[1]), "r"(Al[2]), "r"(Al[3]));
        asm volatile("st.shared.v4.b32 [%0], {%1,%2,%3,%4};" :: "r"(ab + offL1), "r"(Al[4]), "r"(Al[5]), "r"(Al[6]), "r"(Al[7]));
        const uint32_t bbx = ST[buf] + 16384;
#pragma unroll
        for (int gg = 0; gg < CG / 4; gg++) {
            uint32_t BH[4], BL[4];
#pragma unroll
            for (int m = 0; m < 4; m++)
                split2(fb[gg * 4 + m].x, fb[gg * 4 + m].y, BH[m], BL[m]);
            asm volatile("st.shared.v4.b32 [%0], {%1,%2,%3,%4};" :: "r"(bbx + offBH[gg]), "r"(BH[0]), "r"(BH[1]), "r"(BH[2]), "r"(BH[3]));
            asm volatile("st.shared.v4.b32 [%0], {%1,%2,%3,%4};" :: "r"(bbx + offBL[gg]), "r"(BL[0]), "r"(BL[1]), "r"(BL[2]), "r"(BL[3]));
        }
    };

    issue_loads(0);
    convert_store(0);
    __syncthreads();

#pragma unroll 1
    for (int t = 0; t < nst; t++) {
        const int buf = t & 1;
        if (t + 1 < nst) issue_loads(t + 1);

        const uint32_t ab = ST[buf], bb = ST[buf] + 16384;
#pragma unroll
        for (int kk = 0; kk < 2; kk++) {
            const uint32_t khi = (uint32_t)(32 * kk) + co;
            const uint32_t klo = khi + 64;
            uint32_t Ahf[4][4], Alf[4][4];
#pragma unroll
            for (int mi = 0; mi < 4; mi++) {
                ldsm4(Ahf[mi], ab + rA[mi] + (khi ^ xa));
                ldsm4(Alf[mi], ab + rA[mi] + (klo ^ xa));
            }
#pragma unroll
            for (int bj = 0; bj < NB; bj++) {
                uint32_t Bhf[4], Blf[4];
                ldsm4(Bhf, bb + rB[bj] + (khi ^ xa));
                ldsm4(Blf, bb + rB[bj] + (klo ^ xa));
#pragma unroll
                for (int mi = 0; mi < 4; mi++)
#pragma unroll
                    for (int ns = 0; ns < 2; ns++)
                        mma16816(D[mi][bj * 2 + ns], Ahf[mi], Bhf[ns], Bhf[ns + 2]);
#pragma unroll
                for (int mi = 0; mi < 4; mi++)
#pragma unroll
                    for (int ns = 0; ns < 2; ns++)
                        mma16816(D[mi][bj * 2 + ns], Alf[mi], Bhf[ns], Bhf[ns + 2]);
#pragma unroll
                for (int mi = 0; mi < 4; mi++)
#pragma unroll
                    for (int ns = 0; ns < 2; ns++)
                        mma16816(D[mi][bj * 2 + ns], Ahf[mi], Blf[ns], Blf[ns + 2]);
            }
        }

        if (t + 1 < nst) convert_store(buf ^ 1);
        __syncthreads();
    }

    const int colq = nq * (NROWS / 4) + 2 * (lane & 3);
    float* op = out + (size_t)d * 128 * 256 + obase;
#pragma unroll
    for (int mi = 0; mi < 4; mi++) {
        const int b0 = mh * 64 + mi * 16 + (lane >> 2);
#pragma unroll
        for (int nj = 0; nj < 2 * NB; nj++) {
            const int col = colq + nj * 8;
            float2 v0 = make_float2(fmaxf(D[mi][nj][0] * scale, 0.f), fmaxf(D[mi][nj][1] * scale, 0.f));
            float2 v1 = make_float2(fmaxf(D[mi][nj][2] * scale, 0.f), fmaxf(D[mi][nj][3] * scale, 0.f));
            *(float2*)(op + (size_t)b0 * 256 + col)       = v0;
            *(float2*)(op + (size_t)(b0 + 8) * 256 + col) = v1;
        }
    }
}

// ---------------- layers 4..9: lean fp32 FFMA2 kernel ----------------
// CTA = (d, o-block of 32). block 256 = 128 b x 2 og (16 o each).
// Exact fp32 math: out(d,b,o) = relu(scale * sum_{c,k} in(2d+k,b,c) * w(o,c,d,k))
__global__ __launch_bounds__(256)
void lc_tail_ffma(const float* __restrict__ in, const float* __restrict__ w,
                  float* __restrict__ out, int dl, float scale)
{
    __shared__ float  As[2][16][128];     // [k][cc][b]  16KB
    __shared__ float2 Ws[16][2][16];      // [cc][k][opair] 4KB

    const int tid = threadIdx.x;
    const int d   = blockIdx.x;
    const int ob  = blockIdx.y;           // o-block: o in [ob*32, ob*32+32)

    // A loader: thread -> (b = tid>>1, k = tid&1), 16 channels per tile
    const int lb = tid >> 1, lk = tid & 1;
    const float* ap = in + (((size_t)(2 * d + lk)) * 128 + lb) * 256;

    // W loader: thread -> (opair = tid&15, cc = (tid>>4)&15); loads k=0,1
    const int lop = tid & 15, lcc = (tid >> 4) & 15;
    const bool wactive = tid < 256;  // all

    // compute roles
    const int b  = tid & 127;
    const int og = tid >> 7;

    u64 acc[8];
#pragma unroll
    for (int j = 0; j < 8; j++) acc[j] = 0ull;

    float4 sa[4];            // A staging: 16 floats
    float2 sw0a, sw0b, sw1a, sw1b;  // W staging: o-pairs (lop, k) and (lop, k=1)

    auto load_regs = [&](int tile) {
        const int c0 = tile * 16;
        sa[0] = *(const float4*)(ap + c0);
        sa[1] = *(const float4*)(ap + c0 + 4);
        sa[2] = *(const float4*)(ap + c0 + 8);
        sa[3] = *(const float4*)(ap + c0 + 12);
        // W: o = ob*32 + 2*lop (+1), c = c0 + lcc, both k
        const int o0 = ob * 32 + 2 * lop;
        const float2* wp0 = (const float2*)(w + (((size_t)o0 * 256 + c0 + lcc) * dl + d) * 2);
        const float2* wp1 = (const float2*)(w + (((size_t)(o0 + 1) * 256 + c0 + lcc) * dl + d) * 2);
        float2 v0 = *wp0;   // (k0, k1) of o0
        float2 v1 = *wp1;   // (k0, k1) of o0+1
        sw0a = make_float2(v0.x, v1.x);   // k=0 pair
        sw1a = make_float2(v0.y, v1.y);   // k=1 pair
    };
    auto store_smem = [&]() {
#pragma unroll
        for (int i = 0; i < 4; i++)
            *(float4*)&As[lk][/*cc*/ 0 + 0][0] ; // placeholder avoided below
        // A: 16 floats to As[lk][cc][lb]
        const float* s = (const float*)&sa[0];
#pragma unroll
        for (int cc = 0; cc < 16; cc++)
            As[lk][cc][lb] = s[cc];
        Ws[lcc][0][lop] = sw0a;
        Ws[lcc][1][lop] = sw1a;
    };

    load_regs(0);

    for (int tile = 0; tile < 16; tile++) {
        store_smem();
        __syncthreads();
        if (tile + 1 < 16) load_regs(tile + 1);

#pragma unroll
        for (int cc = 0; cc < 16; cc++) {
            u64 a0 = dup2(As[0][cc][b]);
            u64 a1 = dup2(As[1][cc][b]);
            const u64* w0 = (const u64*)&Ws[cc][0][og * 8];
            const u64* w1 = (const u64*)&Ws[cc][1][og * 8];
#pragma unroll
            for (int j = 0; j < 8; j++) {
                fma2(acc[j], a0, w0[j]);
                fma2(acc[j], a1, w1[j]);
            }
        }
        __syncthreads();
    }

    // write: thread covers o = ob*32 + og*16 + [0,16)
    float* op = out + ((size_t)d * 128 + b) * 256 + ob * 32 + og * 16;
#pragma unroll
    for (int j = 0; j < 8; j++) {
        float lo, hi;
        asm("mov.b64 {%0,%1}, %2;" : "=f"(lo), "=f"(hi) : "l"(acc[j]));
        op[2 * j]     = fmaxf(lo * scale, 0.f);
        op[2 * j + 1] = fmaxf(hi * scale, 0.f);
    }
}

// ---------------- head ----------------
__global__ void head_kernel(const float* __restrict__ act, const float* __restrict__ beta,
                            float* __restrict__ out)
{
    const int t = blockIdx.x;
    const int b = threadIdx.x;
    float s = 0.f;
#pragma unroll 8
    for (int o = 0; o < 256; o++)
        s += act[b * 256 + o] * __ldg(&beta[o * 10 + t]);
    out[b * 10 + t] = s * (1.0f / 256.0f);
}

// ---------------- launch ----------------
extern "C" void kernel_launch(void* const* d_in, const int* in_sizes, int n_in,
                              void* d_out, int out_size)
{
    const float* x = (const float*)d_in[0];
    const float* wl[10];
    for (int l = 0; l < 10; l++) wl[l] = (const float*)d_in[1 + l];
    const float* beta = (const float*)d_in[11];
    float* out = (float*)d_out;

    float *bufA, *bufB;
    cudaGetSymbolAddress((void**)&bufA, g_bufA);
    cudaGetSymbolAddress((void**)&bufB, g_bufB);

    cudaFuncSetAttribute(lc_mma<1>, cudaFuncAttributeMaxDynamicSharedMemorySize, 98304);
    cudaFuncSetAttribute(lc_mma<2>, cudaFuncAttributeMaxDynamicSharedMemorySize, 65536);

    const float scale = 0.0625f;

    layer0_kernel<<<512, 256>>>(x, wl[0], bufA);

    lc_mma<1><<<dim3(256, 1), 256, 98304>>>(bufA, wl[1], bufB, 256, 16, scale);
    lc_mma<1><<<dim3(128, 1), 256, 98304>>>(bufB, wl[2], bufA, 128, 16, scale);
    lc_mma<2><<<dim3(64, 2),  256, 65536>>>(bufA, wl[3], bufB, 64, 16, scale);

    // L4..L9: lean FFMA2, grid (dl, 8 o-blocks)
    lc_tail_ffma<<<dim3(32, 8), 256>>>(bufB, wl[4], bufA, 32, scale);
    lc_tail_ffma<<<dim3(16, 8), 256>>>(bufA, wl[5], bufB, 16, scale);
    lc_tail_ffma<<<dim3(8, 8),  256>>>(bufB, wl[6], bufA, 8, scale);
    lc_tail_ffma<<<dim3(4, 8),  256>>>(bufA, wl[7], bufB, 4, scale);
    lc_tail_ffma<<<dim3(2, 8),  256>>>(bufB, wl[8], bufA, 2, scale);
    lc_tail_ffma<<<dim3(1, 8),  256>>>(bufA, wl[9], bufB, 1, scale);

    head_kernel<<<10, 128>>>(bufB, beta, out);
}

// round 17
// speedup vs baseline: 1.4444x; 1.4444x over previous
#include <cuda_runtime.h>
#include <cuda_fp16.h>
#include <cstdint>

typedef unsigned long long u64;

// ---------------- static scratch ----------------
// activations layout: (p, b, c) : act[(p*128 + b)*256 + c]
__device__ __align__(16) float g_bufA[512 * 128 * 256];   // 67 MB
__device__ __align__(16) float g_bufB[256 * 128 * 256];   // 33.5 MB
__device__ __align__(16) float g_part[4194304];           // 16.8 MB split-K partials

// ---------------- helpers ----------------
__device__ __forceinline__ uint32_t s2u(const void* p) {
    uint32_t a;
    asm("{\n\t.reg .u64 t;\n\tcvta.to.shared.u64 t, %1;\n\tcvt.u32.u64 %0, t;\n\t}" : "=r"(a) : "l"(p));
    return a;
}
// pack two f32 -> f16x2: first arg -> low half, second -> high half
__device__ __forceinline__ uint32_t packh(float lo, float hi) {
    uint32_t r;
    asm("cvt.rn.f16x2.f32 %0, %1, %2;" : "=r"(r) : "f"(hi), "f"(lo));
    return r;
}
__device__ __forceinline__ void split2(float x0, float x1, uint32_t& hi, uint32_t& lo) {
    uint32_t h = packh(x0, x1);
    __half2 h2 = *(__half2*)&h;
    lo = packh(x0 - __half2float(h2.x), x1 - __half2float(h2.y));
    hi = h;
}
__device__ __forceinline__ void ldsm4(uint32_t* r, uint32_t addr) {
    asm volatile("ldmatrix.sync.aligned.m8n8.x4.shared.b16 {%0,%1,%2,%3}, [%4];"
        : "=r"(r[0]), "=r"(r[1]), "=r"(r[2]), "=r"(r[3]) : "r"(addr));
}
__device__ __forceinline__ void mma16816(float* d, const uint32_t* a, uint32_t b0, uint32_t b1) {
    asm volatile("mma.sync.aligned.m16n8k16.row.col.f32.f16.f16.f32 "
        "{%0,%1,%2,%3}, {%4,%5,%6,%7}, {%8,%9}, {%0,%1,%2,%3};"
        : "+f"(d[0]), "+f"(d[1]), "+f"(d[2]), "+f"(d[3])
        : "r"(a[0]), "r"(a[1]), "r"(a[2]), "r"(a[3]), "r"(b0), "r"(b1));
}

// ---------------- layer 0 (fp32 exact) ----------------
__global__ void layer0_kernel(const float* __restrict__ x, const float* __restrict__ w0,
                              float* __restrict__ out)
{
    __shared__ float xs[6][128];
    const int d   = blockIdx.x;
    const int tid = threadIdx.x;
#pragma unroll
    for (int i = 0; i < 3; i++) {
        int e = tid + i * 256;
        int ck = e >> 7, b = e & 127;
        int c = ck >> 1, k = ck & 1;
        xs[ck][b] = x[(b * 3 + c) * 1024 + 2 * d + k];
    }
    __syncthreads();
    const int b  = tid & 127;
    const int oh = tid >> 7;
    const float2* w2 = (const float2*)w0;
    for (int o = oh; o < 256; o += 2) {
        float acc = 0.f;
#pragma unroll
        for (int c = 0; c < 3; c++) {
            float2 wv = w2[(o * 3 + c) * 512 + d];
            acc += xs[c * 2 + 0][b] * wv.x + xs[c * 2 + 1][b] * wv.y;
        }
        out[((size_t)d * 128 + b) * 256 + o] = fmaxf(acc * 0.5773502691896258f, 0.f);
    }
}

// ---------------- layers 1..9: warp-mma fp16, P-pass template ----------------
// P=2: A = Ah+Al exact fp16 split, B = fp16(B). D = A_exact * Bh  (err = B rounding)
// P=3: A and B both split; D = Ah*Bh + Al*Bh + Ah*Bl (drops Al*Bl ~ 2^-22)
// in : (p, b, c)  C=256, B=128 ; w : (256, 256, dl, 2)
// CTA: M=128(b) x N=256(all o) x K-slice (nst*32), kappa = 2c+k
// smem stage: A 128x128B + B 256x128B; rows: bytes [0,64) hi plane (2B/kappa),
// [64,128) lo plane; SW128 swizzle per row.
#define SMEM_BYTES 98304

template<int P>
__global__ __launch_bounds__(256)
void lc_mma(const float* __restrict__ in, const float* __restrict__ w,
            float* __restrict__ out, int dl, int nst, float scale, int partial)
{
    extern __shared__ __align__(1024) char smem[];
    const uint32_t sb = s2u(smem);
    const int tid  = threadIdx.x;
    const int wid  = tid >> 5, lane = tid & 31;
    const int d    = blockIdx.x;
    const int s    = blockIdx.y;
    const int cbase = s * nst * 16;

    // ---- A loader roles: row r = b, channel-half h ----
    const int r  = tid >> 1;
    const int h  = tid & 1;
    const float*  a0p = in + ((size_t)(2 * d) * 128 + r) * 256;
    const float*  a1p = a0p + 128 * 256;
    const uint32_t rowb = (uint32_t)r * 128, xs_ = (uint32_t)(r & 7) << 4;
    const uint32_t offH0 = rowb + (((uint32_t)(2 * h) * 16) ^ xs_);
    const uint32_t offH1 = rowb + (((uint32_t)(2 * h + 1) * 16) ^ xs_);
    const uint32_t offL0 = rowb + (((uint32_t)(4 + 2 * h) * 16) ^ xs_);
    const uint32_t offL1 = rowb + (((uint32_t)(5 + 2 * h) * 16) ^ xs_);

    // ---- B loader roles: one thread per o row, 16 channels ----
    const int ob = tid;
    const float2* w2 = (const float2*)w;
    const size_t  wrow = (size_t)ob * 256;
    const uint32_t rowbB = (uint32_t)ob * 128, xsB = (uint32_t)(ob & 7) << 4;
    uint32_t offBH[4], offBL[4];
#pragma unroll
    for (int g = 0; g < 4; g++) {
        offBH[g] = rowbB + (((uint32_t)(g * 16)) ^ xsB);
        offBL[g] = rowbB + (((uint32_t)(64 + g * 16)) ^ xsB);
    }

    const uint32_t ST[2] = { sb, sb + 49152 };

    // ---- compute roles: 2(M) x 4(N) warps, warp tile 64x64 ----
    const int mh = wid & 1, nq = wid >> 1;
    const uint32_t co = (uint32_t)(lane >> 4) * 16;
    const uint32_t xa = (uint32_t)(lane & 7) << 4;
    uint32_t rA[4], rB[4];
#pragma unroll
    for (int mi = 0; mi < 4; mi++) rA[mi] = (uint32_t)(mh * 64 + mi * 16 + (lane & 15)) * 128;
#pragma unroll
    for (int bj = 0; bj < 4; bj++) rB[bj] = (uint32_t)(nq * 64 + bj * 16 + (lane & 15)) * 128;

    float D[4][8][4];
#pragma unroll
    for (int i = 0; i < 4; i++)
#pragma unroll
        for (int j = 0; j < 8; j++)
#pragma unroll
            for (int q = 0; q < 4; q++) D[i][j][q] = 0.f;

    float  fa[16];
    float2 fb[16];

    auto issue_loads = [&](int t) {
        const int c0a = cbase + t * 16 + 8 * h;
        *(float4*)&fa[0]  = *(const float4*)(a0p + c0a);
        *(float4*)&fa[4]  = *(const float4*)(a0p + c0a + 4);
        *(float4*)&fa[8]  = *(const float4*)(a1p + c0a);
        *(float4*)&fa[12] = *(const float4*)(a1p + c0a + 4);
        const int c0b = cbase + t * 16;
#pragma unroll
        for (int j = 0; j < 16; j++)
            fb[j] = w2[(wrow + (size_t)(c0b + j)) * dl + d];
    };

    auto convert_store = [&](int buf) {
        // A: exact hi+lo split (both P=2 and P=3)
        uint32_t Ah[8], Al[8];
#pragma unroll
        for (int j = 0; j < 8; j++)
            split2(fa[j], fa[8 + j], Ah[j], Al[j]);
        const uint32_t ab = ST[buf];
        asm volatile("st.shared.v4.b32 [%0], {%1,%2,%3,%4};" :: "r"(ab + offH0), "r"(Ah[0]), "r"(Ah[1]), "r"(Ah[2]), "r"(Ah[3]));
        asm volatile("st.shared.v4.b32 [%0], {%1,%2,%3,%4};" :: "r"(ab + offH1), "r"(Ah[4]), "r"(Ah[5]), "r"(Ah[6]), "r"(Ah[7]));
        asm volatile("st.shared.v4.b32 [%0], {%1,%2,%3,%4};" :: "r"(ab + offL0), "r"(Al[0]), "r"(Al[1]), "r"(Al[2]), "r"(Al[3]));
        asm volatile("st.shared.v4.b32 [%0], {%1,%2,%3,%4};" :: "r"(ab + offL1), "r"(Al[4]), "r"(Al[5]), "r"(Al[6]), "r"(Al[7]));
        const uint32_t bbx = ST[buf] + 16384;
        if (P == 2) {
#pragma unroll
            for (int g = 0; g < 4; g++) {
                uint32_t BH[4];
#pragma unroll
                for (int m = 0; m < 4; m++)
                    BH[m] = packh(fb[g * 4 + m].x, fb[g * 4 + m].y);
                asm volatile("st.shared.v4.b32 [%0], {%1,%2,%3,%4};" :: "r"(bbx + offBH[g]), "r"(BH[0]), "r"(BH[1]), "r"(BH[2]), "r"(BH[3]));
            }
        } else {
#pragma unroll
            for (int g = 0; g < 4; g++) {
                uint32_t BH[4], BL[4];
#pragma unroll
                for (int m = 0; m < 4; m++)
                    split2(fb[g * 4 + m].x, fb[g * 4 + m].y, BH[m], BL[m]);
                asm volatile("st.shared.v4.b32 [%0], {%1,%2,%3,%4};" :: "r"(bbx + offBH[g]), "r"(BH[0]), "r"(BH[1]), "r"(BH[2]), "r"(BH[3]));
                asm volatile("st.shared.v4.b32 [%0], {%1,%2,%3,%4};" :: "r"(bbx + offBL[g]), "r"(BL[0]), "r"(BL[1]), "r"(BL[2]), "r"(BL[3]));
            }
        }
    };

    issue_loads(0);
    convert_store(0);
    __syncthreads();

#pragma unroll 1
    for (int t = 0; t < nst; t++) {
        const int buf = t & 1;
        if (t + 1 < nst) issue_loads(t + 1);

        const uint32_t ab = ST[buf], bb = ST[buf] + 16384;
#pragma unroll
        for (int kk = 0; kk < 2; kk++) {
            const uint32_t khi = (uint32_t)(32 * kk) + co;
            const uint32_t klo = khi + 64;
            uint32_t Ahf[4][4], Alf[4][4];
#pragma unroll
            for (int mi = 0; mi < 4; mi++) {
                ldsm4(Ahf[mi], ab + rA[mi] + (khi ^ xa));
                ldsm4(Alf[mi], ab + rA[mi] + (klo ^ xa));
            }
#pragma unroll
            for (int bj = 0; bj < 4; bj++) {
                uint32_t Bhf[4];
                ldsm4(Bhf, bb + rB[bj] + (khi ^ xa));
                // sweep 1: Ah*Bh
#pragma unroll
                for (int mi = 0; mi < 4; mi++)
#pragma unroll
                    for (int ns = 0; ns < 2; ns++)
                        mma16816(D[mi][bj * 2 + ns], Ahf[mi], Bhf[ns], Bhf[ns + 2]);
                // sweep 2: Al*Bh
#pragma unroll
                for (int mi = 0; mi < 4; mi++)
#pragma unroll
                    for (int ns = 0; ns < 2; ns++)
                        mma16816(D[mi][bj * 2 + ns], Alf[mi], Bhf[ns], Bhf[ns + 2]);
                if (P == 3) {
                    uint32_t Blf[4];
                    ldsm4(Blf, bb + rB[bj] + (klo ^ xa));
                    // sweep 3: Ah*Bl
#pragma unroll
                    for (int mi = 0; mi < 4; mi++)
#pragma unroll
                        for (int ns = 0; ns < 2; ns++)
                            mma16816(D[mi][bj * 2 + ns], Ahf[mi], Blf[ns], Blf[ns + 2]);
                }
            }
        }

        if (t + 1 < nst) convert_store(buf ^ 1);
        __syncthreads();
    }

    // ---- epilogue ----
    const int colq = nq * 64 + 2 * (lane & 3);
    if (partial) {
        float* pp = g_part + ((size_t)s * dl + d) * 32768;
#pragma unroll
        for (int mi = 0; mi < 4; mi++) {
            const int b0 = mh * 64 + mi * 16 + (lane >> 2);
#pragma unroll
            for (int nj = 0; nj < 8; nj++) {
                const int col = colq + nj * 8;
                *(float2*)(pp + (size_t)b0 * 256 + col)       = make_float2(D[mi][nj][0], D[mi][nj][1]);
                *(float2*)(pp + (size_t)(b0 + 8) * 256 + col) = make_float2(D[mi][nj][2], D[mi][nj][3]);
            }
        }
    } else {
        float* op = out + (size_t)d * 128 * 256;
#pragma unroll
        for (int mi = 0; mi < 4; mi++) {
            const int b0 = mh * 64 + mi * 16 + (lane >> 2);
#pragma unroll
            for (int nj = 0; nj < 8; nj++) {
                const int col = colq + nj * 8;
                float2 v0 = make_float2(fmaxf(D[mi][nj][0] * scale, 0.f), fmaxf(D[mi][nj][1] * scale, 0.f));
                float2 v1 = make_float2(fmaxf(D[mi][nj][2] * scale, 0.f), fmaxf(D[mi][nj][3] * scale, 0.f));
                *(float2*)(op + (size_t)b0 * 256 + col)       = v0;
                *(float2*)(op + (size_t)(b0 + 8) * 256 + col) = v1;
            }
        }
    }
}

// ---------------- split-K reduce + relu ----------------
__global__ void reduce_relu_kernel(const float* __restrict__ part, float* __restrict__ out,
                                   int n, int dl, int S, float scale)
{
    int idx = blockIdx.x * 256 + threadIdx.x;
    if (idx >= n) return;
    const int dd  = idx >> 15;
    const int rem = idx & 32767;
    float sum = 0.f;
    for (int si = 0; si < S; si++)
        sum += part[((size_t)si * dl + dd) * 32768 + rem];
    out[idx] = fmaxf(sum * scale, 0.f);
}

// ---------------- head ----------------
__global__ void head_kernel(const float* __restrict__ act, const float* __restrict__ beta,
                            float* __restrict__ out)
{
    const int t = blockIdx.x;
    const int b = threadIdx.x;
    float s = 0.f;
#pragma unroll 8
    for (int o = 0; o < 256; o++)
        s += act[b * 256 + o] * __ldg(&beta[o * 10 + t]);
    out[b * 10 + t] = s * (1.0f / 256.0f);
}

// ---------------- launch (R10 config; P=2 on L1..L3, P=3 on L4..L9) ----------------
extern "C" void kernel_launch(void* const* d_in, const int* in_sizes, int n_in,
                              void* d_out, int out_size)
{
    const float* x = (const float*)d_in[0];
    const float* wl[10];
    for (int l = 0; l < 10; l++) wl[l] = (const float*)d_in[1 + l];
    const float* beta = (const float*)d_in[11];
    float* out = (float*)d_out;

    float *bufA, *bufB, *part;
    cudaGetSymbolAddress((void**)&bufA, g_bufA);
    cudaGetSymbolAddress((void**)&bufB, g_bufB);
    cudaGetSymbolAddress((void**)&part, g_part);

    cudaFuncSetAttribute(lc_mma<2>, cudaFuncAttributeMaxDynamicSharedMemorySize, SMEM_BYTES);
    cudaFuncSetAttribute(lc_mma<3>, cudaFuncAttributeMaxDynamicSharedMemorySize, SMEM_BYTES);

    layer0_kernel<<<512, 256>>>(x, wl[0], bufA);

    float* cur = bufA;
    float* nxt = bufB;
    int dl = 256;
    const float scale = 0.0625f;
    for (int l = 1; l <= 9; l++) {
        int S;
        if (dl >= 128)     S = 1;
        else if (dl == 64) S = 2;
        else if (dl == 32) S = 4;
        else               S = 8;
        const int nst = 16 / S;
        const bool p2 = (l <= 3);
        if (S == 1) {
            if (p2) lc_mma<2><<<dim3(dl, 1), 256, SMEM_BYTES>>>(cur, wl[l], nxt, dl, nst, scale, 0);
            else    lc_mma<3><<<dim3(dl, 1), 256, SMEM_BYTES>>>(cur, wl[l], nxt, dl, nst, scale, 0);
        } else {
            if (p2) lc_mma<2><<<dim3(dl, S), 256, SMEM_BYTES>>>(cur, wl[l], part, dl, nst, scale, 1);
            else    lc_mma<3><<<dim3(dl, S), 256, SMEM_BYTES>>>(cur, wl[l], part, dl, nst, scale, 1);
            const int n = dl * 32768;
            reduce_relu_kernel<<<(n + 255) / 256, 256>>>(part, nxt, n, dl, S, scale);
        }
        float* tmp = cur; cur = nxt; nxt = tmp;
        dl >>= 1;
    }

    head_kernel<<<10, 128>>>(cur, beta, out);
}